// round 2
// baseline (speedup 1.0000x reference)
#include <cuda_runtime.h>

typedef unsigned long long ull;

// Folded + duplicated weights: each entry is {w, w} packed as 2xf32 in 64 bits,
// so fma.rn.f32x2 can broadcast one weight to both packed points.
__device__ ull g_w1[256];  // W1 = Wa @ Wt   (layer-1 folded), [c][k]
__device__ ull g_w2[256];  // Wb             (layer-2),        [c][k]
__device__ ull g_b1[16];   // b1 = Wa@bt + ba
__device__ ull g_b2[16];   // bb

__device__ __forceinline__ ull fma2(ull a, ull b, ull c) {
    ull d;
    asm("fma.rn.f32x2 %0, %1, %2, %3;" : "=l"(d) : "l"(a), "l"(b), "l"(c));
    return d;
}
__device__ __forceinline__ ull pk2(float lo, float hi) {
    ull d;
    asm("mov.b64 %0, {%1, %2};" : "=l"(d) : "f"(lo), "f"(hi));
    return d;
}
__device__ __forceinline__ float2 up2(ull v) {
    float2 r;
    asm("mov.b64 {%0, %1}, %2;" : "=f"(r.x), "=f"(r.y) : "l"(v));
    return r;
}

// One block, 256 threads. Thread t = (c,k) computes W1[c][k] = sum_j Wa[c][j]*Wt[j][k].
__global__ void fold_weights_kernel(const float* __restrict__ Wt, const float* __restrict__ bt,
                                    const float* __restrict__ Wa, const float* __restrict__ ba,
                                    const float* __restrict__ Wb, const float* __restrict__ bb) {
    int t = threadIdx.x;            // 0..255
    int c = t >> 4;
    int k = t & 15;

    float w1 = 0.0f;
#pragma unroll
    for (int j = 0; j < 16; ++j) w1 += Wa[c * 16 + j] * Wt[j * 16 + k];
    g_w1[t] = pk2(w1, w1);

    float w2 = Wb[c * 16 + k];
    g_w2[t] = pk2(w2, w2);

    if (k == 0) {
        float b1 = ba[c];
#pragma unroll
        for (int j = 0; j < 16; ++j) b1 += Wa[c * 16 + j] * bt[j];
        g_b1[c] = pk2(b1, b1);
        float b2 = bb[c];
        g_b2[c] = pk2(b2, b2);
    }
}

// Each thread processes a pair of points packed into f32x2 lanes. Grid-stride.
__global__ __launch_bounds__(256)
void mlp_pair_kernel(const float* __restrict__ feat, float* __restrict__ out,
                     int npairs, long long n) {
    __shared__ ull s_w1[256];
    __shared__ ull s_w2[256];
    __shared__ ull s_b1[16];
    __shared__ ull s_b2[16];

    int tid = threadIdx.x;
    s_w1[tid] = g_w1[tid];
    s_w2[tid] = g_w2[tid];
    if (tid < 16) { s_b1[tid] = g_b1[tid]; s_b2[tid] = g_b2[tid]; }
    __syncthreads();

    const ulonglong2* w1p = reinterpret_cast<const ulonglong2*>(s_w1);
    const ulonglong2* w2p = reinterpret_cast<const ulonglong2*>(s_w2);

    int stride = gridDim.x * 256;
    for (int i = blockIdx.x * 256 + tid; i < npairs; i += stride) {
        long long iA = 2LL * i;
        long long iB = iA + 1;
        if (iB >= n) iB = iA;   // odd-N tail: duplicate (benign double-write of same value)

        const float4* fA = reinterpret_cast<const float4*>(feat + iA * 16);
        const float4* fB = reinterpret_cast<const float4*>(feat + iB * 16);
        float4 a0 = fA[0], a1 = fA[1], a2 = fA[2], a3 = fA[3];
        float4 b0 = fB[0], b1v = fB[1], b2v = fB[2], b3 = fB[3];

        // Pack x2[k] = {xA[k], xB[k]}
        ull x[16];
        x[0]  = pk2(a0.x, b0.x);  x[1]  = pk2(a0.y, b0.y);
        x[2]  = pk2(a0.z, b0.z);  x[3]  = pk2(a0.w, b0.w);
        x[4]  = pk2(a1.x, b1v.x); x[5]  = pk2(a1.y, b1v.y);
        x[6]  = pk2(a1.z, b1v.z); x[7]  = pk2(a1.w, b1v.w);
        x[8]  = pk2(a2.x, b2v.x); x[9]  = pk2(a2.y, b2v.y);
        x[10] = pk2(a2.z, b2v.z); x[11] = pk2(a2.w, b2v.w);
        x[12] = pk2(a3.x, b3.x);  x[13] = pk2(a3.y, b3.y);
        x[14] = pk2(a3.z, b3.z);  x[15] = pk2(a3.w, b3.w);

        // Layer 1 (folded W1 = Wa@Wt) + ReLU
        ull h[16];
#pragma unroll
        for (int c = 0; c < 16; ++c) {
            ull acc = s_b1[c];
#pragma unroll
            for (int kk = 0; kk < 8; ++kk) {
                ulonglong2 w = w1p[c * 8 + kk];    // LDS.128, broadcast (conflict-free)
                acc = fma2(w.x, x[2 * kk], acc);
                acc = fma2(w.y, x[2 * kk + 1], acc);
            }
            float2 v = up2(acc);
            v.x = fmaxf(v.x, 0.0f);
            v.y = fmaxf(v.y, 0.0f);
            h[c] = pk2(v.x, v.y);
        }

        // Layer 2 (Wb)
        float oa[16], ob[16];
#pragma unroll
        for (int c = 0; c < 16; ++c) {
            ull acc = s_b2[c];
#pragma unroll
            for (int kk = 0; kk < 8; ++kk) {
                ulonglong2 w = w2p[c * 8 + kk];
                acc = fma2(w.x, h[2 * kk], acc);
                acc = fma2(w.y, h[2 * kk + 1], acc);
            }
            float2 v = up2(acc);
            oa[c] = v.x;
            ob[c] = v.y;
        }

        float4* poA = reinterpret_cast<float4*>(out + iA * 16);
        float4* poB = reinterpret_cast<float4*>(out + iB * 16);
        poA[0] = make_float4(oa[0],  oa[1],  oa[2],  oa[3]);
        poA[1] = make_float4(oa[4],  oa[5],  oa[6],  oa[7]);
        poA[2] = make_float4(oa[8],  oa[9],  oa[10], oa[11]);
        poA[3] = make_float4(oa[12], oa[13], oa[14], oa[15]);
        poB[0] = make_float4(ob[0],  ob[1],  ob[2],  ob[3]);
        poB[1] = make_float4(ob[4],  ob[5],  ob[6],  ob[7]);
        poB[2] = make_float4(ob[8],  ob[9],  ob[10], ob[11]);
        poB[3] = make_float4(ob[12], ob[13], ob[14], ob[15]);
    }
}

extern "C" void kernel_launch(void* const* d_in, const int* in_sizes, int n_in,
                              void* d_out, int out_size) {
    // metadata order: features, points, nuv, Wt, bt, Wa, ba, Wb, bb, ranges
    const float* feat = (const float*)d_in[0];
    const float* Wt   = (const float*)d_in[3];
    const float* bt   = (const float*)d_in[4];
    const float* Wa   = (const float*)d_in[5];
    const float* ba   = (const float*)d_in[6];
    const float* Wb   = (const float*)d_in[7];
    const float* bb   = (const float*)d_in[8];
    float* out = (float*)d_out;

    long long n = (long long)in_sizes[0] / 16;   // number of points
    int npairs = (int)((n + 1) / 2);

    fold_weights_kernel<<<1, 256>>>(Wt, bt, Wa, ba, Wb, bb);

    int blocks = (npairs + 255) / 256;
    if (blocks > 1048576) blocks = 1048576;      // grid-stride covers the rest
    mlp_pair_kernel<<<blocks, 256>>>(feat, out, npairs, n);
}

// round 4
// speedup vs baseline: 11.9114x; 11.9114x over previous
#include <cuda_runtime.h>

typedef unsigned long long ull;

// Folded weights (plain layout, no duplication needed for channel-packing):
__device__ float g_w1[256];  // W1 = Wa @ Wt  [c][k], k contiguous
__device__ float g_w2[256];  // Wb            [c][k]
__device__ ull   g_b1[16];   // {b1, 0} pre-packed so acc init needs no add
__device__ ull   g_b2[16];   // {bb, 0}

__device__ __forceinline__ ull fma2(ull a, ull b, ull c) {
    ull d;
    asm("fma.rn.f32x2 %0, %1, %2, %3;" : "=l"(d) : "l"(a), "l"(b), "l"(c));
    return d;
}
__device__ __forceinline__ ull pk2(float lo, float hi) {
    ull d;
    asm("mov.b64 %0, {%1, %2};" : "=l"(d) : "f"(lo), "f"(hi));
    return d;
}
__device__ __forceinline__ float2 up2(ull v) {
    float2 r;
    asm("mov.b64 {%0, %1}, %2;" : "=f"(r.x), "=f"(r.y) : "l"(v));
    return r;
}

// One block, 256 threads. Thread t = (c,k): W1[c][k] = sum_j Wa[c][j]*Wt[j][k].
__global__ void fold_weights_kernel(const float* __restrict__ Wt, const float* __restrict__ bt,
                                    const float* __restrict__ Wa, const float* __restrict__ ba,
                                    const float* __restrict__ Wb, const float* __restrict__ bb) {
    int t = threadIdx.x;            // 0..255
    int c = t >> 4;
    int k = t & 15;

    float w1 = 0.0f;
#pragma unroll
    for (int j = 0; j < 16; ++j) w1 += Wa[c * 16 + j] * Wt[j * 16 + k];
    g_w1[t] = w1;
    g_w2[t] = Wb[t];

    if (k == 0) {
        float b1 = ba[c];
#pragma unroll
        for (int j = 0; j < 16; ++j) b1 += Wa[c * 16 + j] * bt[j];
        g_b1[c] = pk2(b1, 0.0f);
        g_b2[c] = pk2(bb[c], 0.0f);
    }
}

// One point per thread; f32x2 packs CHANNEL pairs (not point pairs), so the
// float4 input load is already in packed form and live state stays ~56 regs.
__global__ __launch_bounds__(256)
void mlp_kernel(const float* __restrict__ feat, float* __restrict__ out, int n) {
    __shared__ float s_w1[256];
    __shared__ float s_w2[256];
    __shared__ ull   s_b1[16];
    __shared__ ull   s_b2[16];

    int tid = threadIdx.x;
    s_w1[tid] = g_w1[tid];
    s_w2[tid] = g_w2[tid];
    if (tid < 16) { s_b1[tid] = g_b1[tid]; s_b2[tid] = g_b2[tid]; }
    __syncthreads();

    const ulonglong2* w1p = reinterpret_cast<const ulonglong2*>(s_w1);  // 4 wts / load
    const ulonglong2* w2p = reinterpret_cast<const ulonglong2*>(s_w2);

    int i = blockIdx.x * 256 + tid;
    if (i >= n) return;

    const float4* f = reinterpret_cast<const float4*>(feat + (long long)i * 16);
    float4 a0 = f[0], a1 = f[1], a2 = f[2], a3 = f[3];

    // Channel pairs: x[q] = {x[2q], x[2q+1]} — aligned pairs straight from float4.
    ull x[8];
    x[0] = pk2(a0.x, a0.y); x[1] = pk2(a0.z, a0.w);
    x[2] = pk2(a1.x, a1.y); x[3] = pk2(a1.z, a1.w);
    x[4] = pk2(a2.x, a2.y); x[5] = pk2(a2.z, a2.w);
    x[6] = pk2(a3.x, a3.y); x[7] = pk2(a3.z, a3.w);

    // Layer 1 (folded W1 = Wa@Wt) + ReLU
    float h[16];
#pragma unroll
    for (int c = 0; c < 16; ++c) {
        ull acc = s_b1[c];                       // {b1, 0}
#pragma unroll
        for (int q = 0; q < 4; ++q) {
            ulonglong2 w = w1p[c * 4 + q];       // LDS.128 broadcast, conflict-free
            acc = fma2(w.x, x[2 * q], acc);
            acc = fma2(w.y, x[2 * q + 1], acc);
        }
        float2 v = up2(acc);
        h[c] = fmaxf(v.x + v.y, 0.0f);
    }

    // Repack hidden activations into channel pairs (x is dead; regs reuse).
    ull hp[8];
#pragma unroll
    for (int q = 0; q < 8; ++q) hp[q] = pk2(h[2 * q], h[2 * q + 1]);

    // Layer 2 (Wb)
    float o[16];
#pragma unroll
    for (int c = 0; c < 16; ++c) {
        ull acc = s_b2[c];                       // {bb, 0}
#pragma unroll
        for (int q = 0; q < 4; ++q) {
            ulonglong2 w = w2p[c * 4 + q];
            acc = fma2(w.x, hp[2 * q], acc);
            acc = fma2(w.y, hp[2 * q + 1], acc);
        }
        float2 v = up2(acc);
        o[c] = v.x + v.y;
    }

    float4* po = reinterpret_cast<float4*>(out + (long long)i * 16);
    po[0] = make_float4(o[0],  o[1],  o[2],  o[3]);
    po[1] = make_float4(o[4],  o[5],  o[6],  o[7]);
    po[2] = make_float4(o[8],  o[9],  o[10], o[11]);
    po[3] = make_float4(o[12], o[13], o[14], o[15]);
}

extern "C" void kernel_launch(void* const* d_in, const int* in_sizes, int n_in,
                              void* d_out, int out_size) {
    // metadata order: features, points, nuv, Wt, bt, Wa, ba, Wb, bb, ranges
    const float* feat = (const float*)d_in[0];
    const float* Wt   = (const float*)d_in[3];
    const float* bt   = (const float*)d_in[4];
    const float* Wa   = (const float*)d_in[5];
    const float* ba   = (const float*)d_in[6];
    const float* Wb   = (const float*)d_in[7];
    const float* bb   = (const float*)d_in[8];
    float* out = (float*)d_out;

    int n = in_sizes[0] / 16;                    // number of points

    fold_weights_kernel<<<1, 256>>>(Wt, bt, Wa, ba, Wb, bb);

    int blocks = (n + 255) / 256;
    mlp_kernel<<<blocks, 256>>>(feat, out, n);
}